// round 9
// baseline (speedup 1.0000x reference)
#include <cuda_runtime.h>
#include <cuda_bf16.h>

// ---------------------------------------------------------------------------
// TensorizedEmbedding: out[b] = core0[d0] x core1[d1] x core2[d2] x core3[d3]
// ROW_DIMS=(8,10,20,20), COL_DIMS=(4,4,6,8), RANKS=(1,16,16,16,1)
//
// R3..R8 finding: per-token latency chain (x load -> L2 table gathers) is the
// ~50us floor; no pipe saturated. Fix: bin tokens by C-combo (idx % 400).
// One block per combo stages C (3KB) ONCE; T01 (80KB) becomes L1-resident.
// Pipeline: init counts -> fused precompute+histogram -> scan -> scatter ->
// binned GEMM. All scratch in __device__ globals; all launches capturable.
// ---------------------------------------------------------------------------

#define NB 400

static __device__ float g_T01[80 * 256];    // [(d0*10+d1)][r2][a]  (a = m0*4+m1)
static __device__ float g_T23[400 * 768];   // [(d2*20+d3)][r2][c]  (c = m2*8+m3)
static __device__ int   g_count[NB];
static __device__ int   g_offset[NB];
static __device__ int   g_cursor[NB];
static __device__ int2  g_binned[32768];    // (t, idx) grouped by combo

__global__ void init_counts() {
    if (threadIdx.x < NB) g_count[threadIdx.x] = 0;
}

// Fused: blocks 0..79 T01, 80..479 T23, 480.. histogram of combos.
__global__ void precompute_hist(const float* __restrict__ core0,
                                const float* __restrict__ core1,
                                const float* __restrict__ core2,
                                const float* __restrict__ core3,
                                const int* __restrict__ x, int B) {
    if (blockIdx.x < 80) {
        int comb = blockIdx.x;
        int d0 = comb / 10, d1 = comb % 10;
        int e  = threadIdx.x;             // 0..255
        int r2 = e >> 4;
        int a  = e & 15;                  // m0*4 + m1
        int m0 = a >> 2, m1 = a & 3;
        float s = 0.f;
#pragma unroll
        for (int r1 = 0; r1 < 16; ++r1) {
            float v0 = core0[(d0 * 4 + m0) * 16 + r1];             // [1,8,4,16]
            float v1 = core1[((r1 * 10 + d1) * 4 + m1) * 16 + r2]; // [16,10,4,16]
            s += v0 * v1;
        }
        g_T01[comb * 256 + r2 * 16 + a] = s;
    } else if (blockIdx.x < 480) {
        int comb = blockIdx.x - 80;       // 0..399
        int d2 = comb / 20, d3 = comb % 20;
        for (int e = threadIdx.x; e < 768; e += blockDim.x) {
            int r2 = e / 48;
            int c  = e - r2 * 48;
            int m2 = c >> 3, m3 = c & 7;
            float s = 0.f;
#pragma unroll
            for (int r3 = 0; r3 < 16; ++r3) {
                float v2 = core2[((r2 * 20 + d2) * 6 + m2) * 16 + r3]; // [16,20,6,16]
                float v3 = core3[(r3 * 20 + d3) * 8 + m3];             // [16,20,8,1]
                s += v2 * v3;
            }
            g_T23[comb * 768 + r2 * 48 + c] = s;
        }
    } else {
        int t = (blockIdx.x - 480) * 256 + threadIdx.x;
        if (t < B) atomicAdd(&g_count[x[t] % NB], 1);
    }
}

// Exclusive prefix sum over 400 counts (single block, Hillis-Steele in smem).
__global__ void scan_counts() {
    __shared__ int s[512];
    int tid = threadIdx.x;                 // 512 threads
    int v = (tid < NB) ? g_count[tid] : 0;
    s[tid] = v;
    __syncthreads();
#pragma unroll
    for (int d = 1; d < 512; d <<= 1) {
        int add = (tid >= d) ? s[tid - d] : 0;
        __syncthreads();
        s[tid] += add;
        __syncthreads();
    }
    if (tid < NB) {
        int excl = s[tid] - v;
        g_offset[tid] = excl;
        g_cursor[tid] = excl;
    }
}

__global__ void scatter_tokens(const int* __restrict__ x, int B) {
    int t = blockIdx.x * 256 + threadIdx.x;
    if (t >= B) return;
    int idx = x[t];
    int c = idx % NB;
    int pos = atomicAdd(&g_cursor[c], 1);
    g_binned[pos] = make_int2(t, idx);
}

// ---------------------------------------------------------------------------

__device__ __forceinline__ unsigned long long pack_dup(float v) {
    unsigned long long r;
    asm("mov.b64 %0, {%1, %1};" : "=l"(r) : "f"(v));
    return r;
}

__device__ __forceinline__ void fma2(unsigned long long& d,
                                     unsigned long long a,
                                     unsigned long long b) {
    asm("fma.rn.f32x2 %0, %1, %2, %0;" : "+l"(d) : "l"(a), "l"(b));
}

__device__ __forceinline__ void stcs64(float* p, unsigned long long v) {
    asm volatile("st.global.cs.b64 [%0], %1;" :: "l"(p), "l"(v) : "memory");
}

// One block per combo; C staged once; warps iterate the bin's tokens.
__global__ __launch_bounds__(256)
void te_binned(float* __restrict__ out) {
    __shared__ float sC[768];        // [r][c] for this combo (3KB)
    __shared__ float sR[8][256];     // per-warp R slice [r][a] (8KB)

    int combo = blockIdx.x;
    int tid   = threadIdx.x;
    int w     = tid >> 5;
    int lane  = tid & 31;

    // Stage C cooperatively (192 float4)
    if (tid < 192)
        ((float4*)sC)[tid] = ((const float4*)(g_T23 + combo * 768))[tid];
    __syncthreads();

    int start = g_offset[combo];
    int n     = g_count[combo];

    // Lane tile: 4 a-rows x 6 c-cols
    int ag = lane >> 3;
    int cg = lane & 7;
    int a0 = ag * 4;
    int c0 = cg * 6;
    const float* baseC = sC + c0;

    // Prefetch first descriptor (lane-uniform broadcast load)
    int2 nxt = make_int2(0, 0);
    if (w < n) nxt = g_binned[start + w];

    for (int i = w; i < n; i += 8) {
        int2 cur = nxt;
        if (i + 8 < n) nxt = g_binned[start + i + 8];   // prefetch next
        int t   = cur.x;
        int d01 = cur.y / NB;    // idx = d01*400 + combo

        // Stage R (1KB, L1-hot: T01 is only 80KB and C no longer thrashes L1)
        __syncwarp();
        const float4* srcR = (const float4*)(g_T01 + d01 * 256);
        float4* dR = (float4*)sR[w];
        dR[lane]      = srcR[lane];
        dR[lane + 32] = srcR[lane + 32];
        __syncwarp();
        const float* baseR = sR[w] + a0;

        unsigned long long acc[4][3];
#pragma unroll
        for (int ii = 0; ii < 4; ++ii)
#pragma unroll
            for (int jj = 0; jj < 3; ++jj) acc[ii][jj] = 0ull;

#pragma unroll
        for (int r = 0; r < 16; ++r) {
            float4 rv = *(const float4*)(baseR + r * 16);          // 4 uniq addrs
            unsigned long long cv0 = *(const unsigned long long*)(baseC + r * 48);
            unsigned long long cv1 = *(const unsigned long long*)(baseC + r * 48 + 2);
            unsigned long long cv2 = *(const unsigned long long*)(baseC + r * 48 + 4);
            unsigned long long r0 = pack_dup(rv.x);
            unsigned long long r1 = pack_dup(rv.y);
            unsigned long long r2 = pack_dup(rv.z);
            unsigned long long r3 = pack_dup(rv.w);
            fma2(acc[0][0], r0, cv0); fma2(acc[0][1], r0, cv1); fma2(acc[0][2], r0, cv2);
            fma2(acc[1][0], r1, cv0); fma2(acc[1][1], r1, cv1); fma2(acc[1][2], r1, cv2);
            fma2(acc[2][0], r2, cv0); fma2(acc[2][1], r2, cv1); fma2(acc[2][2], r2, cv2);
            fma2(acc[3][0], r3, cv0); fma2(acc[3][1], r3, cv1); fma2(acc[3][2], r3, cv2);
        }

        float* op = out + (size_t)t * 768 + c0;
#pragma unroll
        for (int ai = 0; ai < 4; ++ai) {
            float* rp = op + (a0 + ai) * 48;
            stcs64(rp,     acc[ai][0]);
            stcs64(rp + 2, acc[ai][1]);
            stcs64(rp + 4, acc[ai][2]);
        }
    }
}

// ---------------------------------------------------------------------------

extern "C" void kernel_launch(void* const* d_in, const int* in_sizes, int n_in,
                              void* d_out, int out_size) {
    // Identify inputs by element count (robust to ordering):
    // x: B (=32768), core0: 512, core1: 10240, core2: 30720, core3: 2560
    const int*   x  = nullptr;  int B = 0;
    const float* c0 = nullptr;
    const float* c1 = nullptr;
    const float* c2 = nullptr;
    const float* c3 = nullptr;
    for (int i = 0; i < n_in; ++i) {
        switch (in_sizes[i]) {
            case 512:   c0 = (const float*)d_in[i]; break;
            case 10240: c1 = (const float*)d_in[i]; break;
            case 30720: c2 = (const float*)d_in[i]; break;
            case 2560:  c3 = (const float*)d_in[i]; break;
            default:    x  = (const int*)d_in[i]; B = in_sizes[i]; break;
        }
    }
    if (B > 32768) B = 32768;   // scratch bound (problem uses B=32768)

    int tokBlocks = (B + 255) / 256;
    init_counts<<<1, 512>>>();
    precompute_hist<<<480 + tokBlocks, 256>>>(c0, c1, c2, c3, x, B);
    scan_counts<<<1, 512>>>();
    scatter_tokens<<<tokBlocks, 256>>>(x, B);
    te_binned<<<NB, 256>>>((float*)d_out);
}

// round 10
// speedup vs baseline: 1.3331x; 1.3331x over previous
#include <cuda_runtime.h>
#include <cuda_bf16.h>

// ---------------------------------------------------------------------------
// TensorizedEmbedding: out[b] = core0[d0] x core1[d1] x core2[d2] x core3[d3]
// ROW_DIMS=(8,10,20,20), COL_DIMS=(4,4,6,8), RANKS=(1,16,16,16,1)
//
// Findings R3..R9: token-parallel kernel is latency-bound on the per-token
// chain (x load -> table gather -> stage); no pipe saturated. Binning (R9)
// removed the chain but aux kernels cost more than it saved.
// This version HIDES the chain: each warp owns 4 sequential tokens and
// software-pipelines the next token's table stage (cp.async.cg, double
// buffered in SMEM) under the current token's 16x48x16 GEMM.
// cp.async is correct here (unlike R4) because its L2 latency is overlapped.
// ---------------------------------------------------------------------------

static __device__ float g_T01[80 * 256];    // [(d0*10+d1)][r2][a]  (a = m0*4+m1)
static __device__ float g_T23[400 * 768];   // [(d2*20+d3)][r2][c]  (c = m2*8+m3)

// Fused precompute: blocks 0..79 build T01, blocks 80..479 build T23.
__global__ void precompute_tables(const float* __restrict__ core0,
                                  const float* __restrict__ core1,
                                  const float* __restrict__ core2,
                                  const float* __restrict__ core3) {
    if (blockIdx.x < 80) {
        int comb = blockIdx.x;
        int d0 = comb / 10, d1 = comb % 10;
        int e  = threadIdx.x;             // 0..255
        int r2 = e >> 4;
        int a  = e & 15;                  // m0*4 + m1
        int m0 = a >> 2, m1 = a & 3;
        float s = 0.f;
#pragma unroll
        for (int r1 = 0; r1 < 16; ++r1) {
            float v0 = core0[(d0 * 4 + m0) * 16 + r1];             // [1,8,4,16]
            float v1 = core1[((r1 * 10 + d1) * 4 + m1) * 16 + r2]; // [16,10,4,16]
            s += v0 * v1;
        }
        g_T01[comb * 256 + r2 * 16 + a] = s;
    } else {
        int comb = blockIdx.x - 80;       // 0..399
        int d2 = comb / 20, d3 = comb % 20;
        for (int e = threadIdx.x; e < 768; e += blockDim.x) {
            int r2 = e / 48;
            int c  = e - r2 * 48;
            int m2 = c >> 3, m3 = c & 7;
            float s = 0.f;
#pragma unroll
            for (int r3 = 0; r3 < 16; ++r3) {
                float v2 = core2[((r2 * 20 + d2) * 6 + m2) * 16 + r3]; // [16,20,6,16]
                float v3 = core3[(r3 * 20 + d3) * 8 + m3];             // [16,20,8,1]
                s += v2 * v3;
            }
            g_T23[comb * 768 + r2 * 48 + c] = s;
        }
    }
}

// ---------------------------------------------------------------------------

#define T_PER_WARP 4          // tokens per warp (pipeline depth amortization)
#define WARPS 8               // warps per block
// per-warp smem: 2 x (256 R + 768 C) floats = 8KB; block = 64KB (dynamic)

__device__ __forceinline__ unsigned long long pack_dup(float v) {
    unsigned long long r;
    asm("mov.b64 %0, {%1, %1};" : "=l"(r) : "f"(v));
    return r;
}

__device__ __forceinline__ void fma2(unsigned long long& d,
                                     unsigned long long a,
                                     unsigned long long b) {
    asm("fma.rn.f32x2 %0, %1, %2, %0;" : "+l"(d) : "l"(a), "l"(b));
}

__device__ __forceinline__ void stcs64(float* p, unsigned long long v) {
    asm volatile("st.global.cs.b64 [%0], %1;" :: "l"(p), "l"(v) : "memory");
}

__device__ __forceinline__ unsigned smem_u32(const void* p) {
    unsigned a;
    asm("{ .reg .u64 t; cvta.to.shared.u64 t, %1; cvt.u32.u64 %0, t; }"
        : "=r"(a) : "l"(p));
    return a;
}

__device__ __forceinline__ void cpasync16(unsigned dst, const void* src) {
    asm volatile("cp.async.cg.shared.global [%0], [%1], 16;"
                 :: "r"(dst), "l"(src) : "memory");
}

__global__ __launch_bounds__(256)
void te_pipelined(const int* __restrict__ x, float* __restrict__ out, int B) {
    extern __shared__ float smem[];     // [WARPS][2048]: per warp R0 R1 C0 C1

    int w    = threadIdx.x >> 5;
    int lane = threadIdx.x & 31;
    int base = (blockIdx.x * WARPS + w) * T_PER_WARP;

    float* wbuf = smem + w * 2048;      // R buf b at +b*256, C buf b at +512+b*768
    unsigned wR = smem_u32(wbuf);           // byte address of R0
    unsigned wC = smem_u32(wbuf + 512);     // byte address of C0
    if (base >= B) return;

    // One coalesced x load per warp, distributed by shfl.
    int myx = 0;
    if (lane < T_PER_WARP && base + lane < B) myx = x[base + lane];

    // Lane tile: 4 a-rows x 6 c-cols
    int ag = lane >> 3;
    int cg = lane & 7;
    int a0 = ag * 4;
    int c0 = cg * 6;

    // ---- prefetch token 0 into buffer 0 ----
    {
        int idx = __shfl_sync(0xffffffffu, myx, 0);
        int d01 = idx / 400, combo = idx - d01 * 400;
        const float* srcR = g_T01 + d01 * 256;
        const float* srcC = g_T23 + combo * 768;
        cpasync16(wR + lane * 16,       srcR + lane * 4);
        cpasync16(wR + 512 + lane * 16, srcR + 128 + lane * 4);
#pragma unroll
        for (int k = 0; k < 6; ++k)
            cpasync16(wC + (lane + 32 * k) * 16, srcC + (lane + 32 * k) * 4);
        asm volatile("cp.async.commit_group;" ::: "memory");
    }

#pragma unroll
    for (int i = 0; i < T_PER_WARP; ++i) {
        int t = base + i;
        if (t >= B) break;
        int buf = i & 1;

        // Prefetch next token into the other buffer, then wait for current.
        if (i + 1 < T_PER_WARP && t + 1 < B) {
            int nb  = (i + 1) & 1;
            int idx = __shfl_sync(0xffffffffu, myx, i + 1);
            int d01 = idx / 400, combo = idx - d01 * 400;
            const float* srcR = g_T01 + d01 * 256;
            const float* srcC = g_T23 + combo * 768;
            unsigned dR = wR + nb * 1024;
            unsigned dC = wC + nb * 3072;
            cpasync16(dR + lane * 16,       srcR + lane * 4);
            cpasync16(dR + 512 + lane * 16, srcR + 128 + lane * 4);
#pragma unroll
            for (int k = 0; k < 6; ++k)
                cpasync16(dC + (lane + 32 * k) * 16, srcC + (lane + 32 * k) * 4);
            asm volatile("cp.async.commit_group;" ::: "memory");
            asm volatile("cp.async.wait_group 1;" ::: "memory");   // current done
        } else {
            asm volatile("cp.async.wait_group 0;" ::: "memory");
        }
        __syncwarp();

        const float* baseR = wbuf + buf * 256 + a0;
        const float* baseC = wbuf + 512 + buf * 768 + c0;

        unsigned long long acc[4][3];
#pragma unroll
        for (int ii = 0; ii < 4; ++ii)
#pragma unroll
            for (int jj = 0; jj < 3; ++jj) acc[ii][jj] = 0ull;

#pragma unroll
        for (int r = 0; r < 16; ++r) {
            // R: LDS.128, 4 unique addrs/warp (broadcast); C: 3x LDS.64,
            // 8 unique addrs each, bank-disjoint.
            float4 rv = *(const float4*)(baseR + r * 16);
            unsigned long long cv0 = *(const unsigned long long*)(baseC + r * 48);
            unsigned long long cv1 = *(const unsigned long long*)(baseC + r * 48 + 2);
            unsigned long long cv2 = *(const unsigned long long*)(baseC + r * 48 + 4);
            unsigned long long r0 = pack_dup(rv.x);
            unsigned long long r1 = pack_dup(rv.y);
            unsigned long long r2 = pack_dup(rv.z);
            unsigned long long r3 = pack_dup(rv.w);
            fma2(acc[0][0], r0, cv0); fma2(acc[0][1], r0, cv1); fma2(acc[0][2], r0, cv2);
            fma2(acc[1][0], r1, cv0); fma2(acc[1][1], r1, cv1); fma2(acc[1][2], r1, cv2);
            fma2(acc[2][0], r2, cv0); fma2(acc[2][1], r2, cv1); fma2(acc[2][2], r2, cv2);
            fma2(acc[3][0], r3, cv0); fma2(acc[3][1], r3, cv1); fma2(acc[3][2], r3, cv2);
        }

        float* op = out + (size_t)t * 768 + c0;
#pragma unroll
        for (int ai = 0; ai < 4; ++ai) {
            float* rp = op + (a0 + ai) * 48;
            stcs64(rp,     acc[ai][0]);
            stcs64(rp + 2, acc[ai][1]);
            stcs64(rp + 4, acc[ai][2]);
        }
    }
}

// ---------------------------------------------------------------------------

extern "C" void kernel_launch(void* const* d_in, const int* in_sizes, int n_in,
                              void* d_out, int out_size) {
    // Identify inputs by element count (robust to ordering):
    // x: B (=32768), core0: 512, core1: 10240, core2: 30720, core3: 2560
    const int*   x  = nullptr;  int B = 0;
    const float* c0 = nullptr;
    const float* c1 = nullptr;
    const float* c2 = nullptr;
    const float* c3 = nullptr;
    for (int i = 0; i < n_in; ++i) {
        switch (in_sizes[i]) {
            case 512:   c0 = (const float*)d_in[i]; break;
            case 10240: c1 = (const float*)d_in[i]; break;
            case 30720: c2 = (const float*)d_in[i]; break;
            case 2560:  c3 = (const float*)d_in[i]; break;
            default:    x  = (const int*)d_in[i]; B = in_sizes[i]; break;
        }
    }

    precompute_tables<<<480, 256>>>(c0, c1, c2, c3);

    static bool attr_set = false;
    if (!attr_set) {
        cudaFuncSetAttribute(te_pipelined,
                             cudaFuncAttributeMaxDynamicSharedMemorySize,
                             WARPS * 2048 * sizeof(float));
        attr_set = true;
    }

    int tokPerBlock = WARPS * T_PER_WARP;           // 32
    int blocks = (B + tokPerBlock - 1) / tokPerBlock;
    te_pipelined<<<blocks, 256, WARPS * 2048 * sizeof(float)>>>(
        x, (float*)d_out, B);
}

// round 11
// speedup vs baseline: 1.7994x; 1.3497x over previous
#include <cuda_runtime.h>
#include <cuda_bf16.h>

// ---------------------------------------------------------------------------
// TensorizedEmbedding: out[b] = core0[d0] x core1[d1] x core2[d2] x core3[d3]
// ROW_DIMS=(8,10,20,20), COL_DIMS=(4,4,6,8), RANKS=(1,16,16,16,1)
//
// R3..R10: five scalar variants all ~51us; per-token scalar datapath (~370
// instr) is the invariant. This version maps the per-token 16x48x16 GEMM onto
// tensor cores: 12x mma.sync.m16n8k8.tf32. Tables are precomputed DIRECTLY in
// MMA fragment layout, pre-rounded to tf32 (cvt.rna), so per token:
// 8 coalesced LDG.128 (fragments, no smem/syncs) + 12 HMMA + 12 STG.64.
// fp32 accumulate; expected norm rel_err ~3e-4 (<1e-3).
// ---------------------------------------------------------------------------

// Fragment tables.
// g_FA[comb01][kt=2][lane=32][reg=4]: A fragments (m16k8, row.col spec):
//   reg0: A[g   ][tq  ], reg1: A[g+8 ][tq  ], reg2: A[g   ][tq+4], reg3: A[g+8][tq+4]
//   where g=lane>>2, tq=lane&3, A[a][r_local], r = kt*8 + r_local.
// g_FB[comb23][nt=6][lane=32][reg=4]: B fragments (k8n8 col-major spec),
//   two k-tiles packed per float4: reg0=kt0.b0, reg1=kt0.b1, reg2=kt1.b0, reg3=kt1.b1
//   b0: B[k=tq][n=g], b1: B[k=tq+4][n=g]; global k = kt*8+..., n = nt*8+g.
static __device__ float g_FA[80 * 2 * 32 * 4];     // 80 KB
static __device__ float g_FB[400 * 6 * 32 * 4];    // 1.2 MB

__device__ __forceinline__ float tf32_rna(float x) {
    unsigned u;
    asm("cvt.rna.tf32.f32 %0, %1;" : "=r"(u) : "f"(x));
    return __uint_as_float(u);
}

// Fused precompute into fragment layout: blocks 0..79 FA, 80..479 FB.
__global__ void precompute_frags(const float* __restrict__ core0,
                                 const float* __restrict__ core1,
                                 const float* __restrict__ core2,
                                 const float* __restrict__ core3) {
    if (blockIdx.x < 80) {
        int comb = blockIdx.x;                 // d0*10 + d1
        int d0 = comb / 10, d1 = comb % 10;
        int e   = threadIdx.x;                 // 0..255 covers [kt][lane][reg]
        int kt  = e >> 7;
        int l   = (e >> 2) & 31;
        int reg = e & 3;
        int row = (l >> 2) + (reg & 1) * 8;    // a (m-dim, 0..15)
        int col = (l & 3) + (reg >> 1) * 4;    // r within k-tile
        int r2  = kt * 8 + col;
        int m0  = row >> 2, m1 = row & 3;
        float s = 0.f;
#pragma unroll
        for (int r1 = 0; r1 < 16; ++r1) {
            float v0 = core0[(d0 * 4 + m0) * 16 + r1];             // [1,8,4,16]
            float v1 = core1[((r1 * 10 + d1) * 4 + m1) * 16 + r2]; // [16,10,4,16]
            s += v0 * v1;
        }
        g_FA[((comb * 2 + kt) * 32 + l) * 4 + reg] = tf32_rna(s);
    } else {
        int comb = blockIdx.x - 80;            // d2*20 + d3
        int d2 = comb / 20, d3 = comb % 20;
        for (int e = threadIdx.x; e < 768; e += blockDim.x) {
            int nt  = e / 128;                 // 0..5
            int rr  = e & 127;
            int l   = rr >> 2;
            int reg = rr & 3;
            int kt  = reg >> 1, bb = reg & 1;
            int k   = (l & 3) + bb * 4 + kt * 8;   // r2 (k-dim, 0..15)
            int n   = nt * 8 + (l >> 2);           // c  (n-dim, 0..47)
            int m2  = n >> 3, m3 = n & 7;
            float s = 0.f;
#pragma unroll
            for (int r3 = 0; r3 < 16; ++r3) {
                float v2 = core2[((k * 20 + d2) * 6 + m2) * 16 + r3]; // [16,20,6,16]
                float v3 = core3[(r3 * 20 + d3) * 8 + m3];            // [16,20,8,1]
                s += v2 * v3;
            }
            g_FB[((comb * 6 + nt) * 32 + l) * 4 + reg] = tf32_rna(s);
        }
    }
}

// ---------------------------------------------------------------------------

__device__ __forceinline__ void mma_tf32(float* c, float4 a, float b0, float b1) {
    asm volatile(
        "mma.sync.aligned.m16n8k8.row.col.f32.tf32.tf32.f32 "
        "{%0,%1,%2,%3},{%4,%5,%6,%7},{%8,%9},{%0,%1,%2,%3};"
        : "+f"(c[0]), "+f"(c[1]), "+f"(c[2]), "+f"(c[3])
        : "r"(__float_as_uint(a.x)), "r"(__float_as_uint(a.y)),
          "r"(__float_as_uint(a.z)), "r"(__float_as_uint(a.w)),
          "r"(__float_as_uint(b0)),  "r"(__float_as_uint(b1)));
}

__device__ __forceinline__ void stcs64_2f(float* p, float lo, float hi) {
    unsigned long long v;
    asm("mov.b64 %0, {%1, %2};" : "=l"(v) : "f"(lo), "f"(hi));
    asm volatile("st.global.cs.b64 [%0], %1;" :: "l"(p), "l"(v) : "memory");
}

#define T_PER_WARP 4
#define WARPS 8

__global__ __launch_bounds__(256)
void te_mma(const int* __restrict__ x, float* __restrict__ out, int B) {
    int w    = threadIdx.x >> 5;
    int lane = threadIdx.x & 31;
    int base = (blockIdx.x * WARPS + w) * T_PER_WARP;
    if (base >= B) return;

    // Coalesced x load for this warp's 4 tokens, distributed via shfl.
    int myx = 0;
    if (lane < T_PER_WARP && base + lane < B) myx = x[base + lane];

    int g  = lane >> 2;     // group id (row within fragment)
    int tq = lane & 3;      // thread-in-group (col pair index)

#pragma unroll
    for (int i = 0; i < T_PER_WARP; ++i) {
        int t = base + i;
        if (t >= B) break;
        int idx  = __shfl_sync(0xffffffffu, myx, i);
        int d01  = idx / 400;
        int comb = idx - d01 * 400;

        const float4* pA = (const float4*)g_FA + (size_t)d01 * 2 * 32 + lane;
        const float4* pB = (const float4*)g_FB + (size_t)comb * 6 * 32 + lane;

        // A fragments for both k-tiles (coalesced 512B per LDG across warp)
        float4 ak0 = __ldg(pA);
        float4 ak1 = __ldg(pA + 32);

        float acc[6][4];
#pragma unroll
        for (int nt = 0; nt < 6; ++nt)
#pragma unroll
            for (int j = 0; j < 4; ++j) acc[nt][j] = 0.f;

#pragma unroll
        for (int nt = 0; nt < 6; ++nt) {
            float4 b = __ldg(pB + nt * 32);
            mma_tf32(acc[nt], ak0, b.x, b.y);   // k-tile 0
            mma_tf32(acc[nt], ak1, b.z, b.w);   // k-tile 1
        }

        // D layout: c0,c1 -> row g, cols tq*2, tq*2+1; c2,c3 -> row g+8.
        // Per STG: 8 rows x 32B fully-written sectors (perfect efficiency).
        float* op = out + (size_t)t * 768 + g * 48 + tq * 2;
#pragma unroll
        for (int nt = 0; nt < 6; ++nt) {
            stcs64_2f(op + nt * 8,       acc[nt][0], acc[nt][1]);
            stcs64_2f(op + nt * 8 + 384, acc[nt][2], acc[nt][3]);  // +8 rows
        }
    }
}

// ---------------------------------------------------------------------------

extern "C" void kernel_launch(void* const* d_in, const int* in_sizes, int n_in,
                              void* d_out, int out_size) {
    // Identify inputs by element count (robust to ordering):
    // x: B (=32768), core0: 512, core1: 10240, core2: 30720, core3: 2560
    const int*   x  = nullptr;  int B = 0;
    const float* c0 = nullptr;
    const float* c1 = nullptr;
    const float* c2 = nullptr;
    const float* c3 = nullptr;
    for (int i = 0; i < n_in; ++i) {
        switch (in_sizes[i]) {
            case 512:   c0 = (const float*)d_in[i]; break;
            case 10240: c1 = (const float*)d_in[i]; break;
            case 30720: c2 = (const float*)d_in[i]; break;
            case 2560:  c3 = (const float*)d_in[i]; break;
            default:    x  = (const int*)d_in[i]; B = in_sizes[i]; break;
        }
    }

    precompute_frags<<<480, 256>>>(c0, c1, c2, c3);

    int tokPerBlock = WARPS * T_PER_WARP;            // 32
    int blocks = (B + tokPerBlock - 1) / tokPerBlock;
    te_mma<<<blocks, 256>>>(x, (float*)d_out, B);
}

// round 12
// speedup vs baseline: 1.8956x; 1.0535x over previous
#include <cuda_runtime.h>
#include <cuda_fp16.h>

// ---------------------------------------------------------------------------
// TensorizedEmbedding: out[b] = core0[d0] x core1[d1] x core2[d2] x core3[d3]
// ROW_DIMS=(8,10,20,20), COL_DIMS=(4,4,6,8), RANKS=(1,16,16,16,1)
//
// R11 (tf32 MMA) won: main kernel is now memory-traffic-bound (134MB frag
// reads + 100MB output writes). fp16 has the SAME 10-bit mantissa as tf32,
// so switching fragments to fp16 + m16n8k16 halves read traffic, MMA count,
// and LDG count at zero precision cost (fp32 accumulate kept).
// Per token: 4x LDG.128 + 6x HMMA.16816 + 12x STG.64.
// ---------------------------------------------------------------------------

// Fragment tables (fp16, MMA m16n8k16 register layout).
// g_FA[comb01][lane=32][reg=4][half=2]  (512B per combo, 40KB total)
//   A (m16 x k16, row): a0=(g,tq*2|+1) a1=(g+8,..) a2=(g,tq*2+8|+9) a3=(g+8,..)
// g_FB[comb23][ntp=3][lane=32][reg=4][half=2] (1.5KB per combo, 600KB total)
//   per nt-pair: {nt_even.b0, nt_even.b1, nt_odd.b0, nt_odd.b1}
//   B (k16 x n8, col): b0=(k=tq*2|+1, n=g) b1=(k=tq*2+8|+9, n=g)
static __device__ __half g_FA[80 * 256];
static __device__ __half g_FB[400 * 768];

// Fused precompute into fp16 fragment layout: blocks 0..79 FA, 80..479 FB.
__global__ void precompute_frags(const float* __restrict__ core0,
                                 const float* __restrict__ core1,
                                 const float* __restrict__ core2,
                                 const float* __restrict__ core3) {
    if (blockIdx.x < 80) {
        int comb = blockIdx.x;                 // d0*10 + d1
        int d0 = comb / 10, d1 = comb % 10;
        int e   = threadIdx.x;                 // 0..255 = [lane][reg][half]
        int l   = e >> 3;
        int rr  = (e >> 1) & 3;
        int h   = e & 1;
        int row = (l >> 2) + (rr & 1) * 8;             // a (m-dim)
        int r2  = (l & 3) * 2 + h + (rr >> 1) * 8;     // k-dim
        int m0  = row >> 2, m1 = row & 3;
        float s = 0.f;
#pragma unroll
        for (int r1 = 0; r1 < 16; ++r1) {
            float v0 = core0[(d0 * 4 + m0) * 16 + r1];             // [1,8,4,16]
            float v1 = core1[((r1 * 10 + d1) * 4 + m1) * 16 + r2]; // [16,10,4,16]
            s += v0 * v1;
        }
        g_FA[comb * 256 + e] = __float2half_rn(s);
    } else {
        int comb = blockIdx.x - 80;            // d2*20 + d3
        int d2 = comb / 20, d3 = comb % 20;
        for (int e = threadIdx.x; e < 768; e += blockDim.x) {
            int ntp = e >> 8;                  // 0..2 (nt pair)
            int r8  = e & 255;
            int l   = r8 >> 3;
            int rr  = (r8 >> 1) & 3;
            int h   = r8 & 1;
            int nt  = ntp * 2 + (rr >> 1);
            int brg = rr & 1;
            int k   = (l & 3) * 2 + h + brg * 8;   // r2 (k-dim)
            int n   = nt * 8 + (l >> 2);           // c  (n-dim)
            int m2  = n >> 3, m3 = n & 7;
            float s = 0.f;
#pragma unroll
            for (int r3 = 0; r3 < 16; ++r3) {
                float v2 = core2[((k * 20 + d2) * 6 + m2) * 16 + r3]; // [16,20,6,16]
                float v3 = core3[(r3 * 20 + d3) * 8 + m3];            // [16,20,8,1]
                s += v2 * v3;
            }
            g_FB[comb * 768 + e] = __float2half_rn(s);
        }
    }
}

// ---------------------------------------------------------------------------

__device__ __forceinline__ void mma_f16(float* c, float4 a,
                                        unsigned b0, unsigned b1) {
    asm volatile(
        "mma.sync.aligned.m16n8k16.row.col.f32.f16.f16.f32 "
        "{%0,%1,%2,%3},{%4,%5,%6,%7},{%8,%9},{%0,%1,%2,%3};"
        : "+f"(c[0]), "+f"(c[1]), "+f"(c[2]), "+f"(c[3])
        : "r"(__float_as_uint(a.x)), "r"(__float_as_uint(a.y)),
          "r"(__float_as_uint(a.z)), "r"(__float_as_uint(a.w)),
          "r"(b0), "r"(b1));
}

__device__ __forceinline__ void stcs64_2f(float* p, float lo, float hi) {
    unsigned long long v;
    asm("mov.b64 %0, {%1, %2};" : "=l"(v) : "f"(lo), "f"(hi));
    asm volatile("st.global.cs.b64 [%0], %1;" :: "l"(p), "l"(v) : "memory");
}

#define T_PER_WARP 4
#define WARPS 8

__global__ __launch_bounds__(256)
void te_mma(const int* __restrict__ x, float* __restrict__ out, int B) {
    int w    = threadIdx.x >> 5;
    int lane = threadIdx.x & 31;
    int base = (blockIdx.x * WARPS + w) * T_PER_WARP;
    if (base >= B) return;

    // Coalesced x load for this warp's 4 tokens, distributed via shfl.
    int myx = 0;
    if (lane < T_PER_WARP && base + lane < B) myx = x[base + lane];

    int g  = lane >> 2;     // fragment row group
    int tq = lane & 3;      // thread-in-group

#pragma unroll
    for (int i = 0; i < T_PER_WARP; ++i) {
        int t = base + i;
        if (t >= B) break;
        int idx  = __shfl_sync(0xffffffffu, myx, i);
        int d01  = idx / 400;
        int comb = idx - d01 * 400;

        // A: one LDG.128 (512B/warp); B: three LDG.128 (nt pairs, 512B each)
        const float4* pA = (const float4*)g_FA + (size_t)d01 * 32 + lane;
        const float4* pB = (const float4*)g_FB + (size_t)comb * 96 + lane;

        float4 af = __ldg(pA);
        float4 b0 = __ldg(pB);
        float4 b1 = __ldg(pB + 32);
        float4 b2 = __ldg(pB + 64);

        float acc[6][4];
#pragma unroll
        for (int nt = 0; nt < 6; ++nt)
#pragma unroll
            for (int j = 0; j < 4; ++j) acc[nt][j] = 0.f;

        mma_f16(acc[0], af, __float_as_uint(b0.x), __float_as_uint(b0.y));
        mma_f16(acc[1], af, __float_as_uint(b0.z), __float_as_uint(b0.w));
        mma_f16(acc[2], af, __float_as_uint(b1.x), __float_as_uint(b1.y));
        mma_f16(acc[3], af, __float_as_uint(b1.z), __float_as_uint(b1.w));
        mma_f16(acc[4], af, __float_as_uint(b2.x), __float_as_uint(b2.y));
        mma_f16(acc[5], af, __float_as_uint(b2.z), __float_as_uint(b2.w));

        // D: c0,c1 -> row g cols tq*2,tq*2+1; c2,c3 -> row g+8.
        // Each (g,nt) group of 4 lanes fills one 32B sector completely.
        float* op = out + (size_t)t * 768 + g * 48 + tq * 2;
#pragma unroll
        for (int nt = 0; nt < 6; ++nt) {
            stcs64_2f(op + nt * 8,       acc[nt][0], acc[nt][1]);
            stcs64_2f(op + nt * 8 + 384, acc[nt][2], acc[nt][3]);  // +8 rows
        }
    }
}

// ---------------------------------------------------------------------------

extern "C" void kernel_launch(void* const* d_in, const int* in_sizes, int n_in,
                              void* d_out, int out_size) {
    // Identify inputs by element count (robust to ordering):
    // x: B (=32768), core0: 512, core1: 10240, core2: 30720, core3: 2560
    const int*   x  = nullptr;  int B = 0;
    const float* c0 = nullptr;
    const float* c1 = nullptr;
    const float* c2 = nullptr;
    const float* c3 = nullptr;
    for (int i = 0; i < n_in; ++i) {
        switch (in_sizes[i]) {
            case 512:   c0 = (const float*)d_in[i]; break;
            case 10240: c1 = (const float*)d_in[i]; break;
            case 30720: c2 = (const float*)d_in[i]; break;
            case 2560:  c3 = (const float*)d_in[i]; break;
            default:    x  = (const int*)d_in[i]; B = in_sizes[i]; break;
        }
    }

    precompute_frags<<<480, 256>>>(c0, c1, c2, c3);

    int tokPerBlock = WARPS * T_PER_WARP;            // 32
    int blocks = (B + tokPerBlock - 1) / tokPerBlock;
    te_mma<<<blocks, 256>>>(x, (float*)d_out, B);
}

// round 14
// speedup vs baseline: 2.2488x; 1.1863x over previous
#include <cuda_runtime.h>
#include <cuda_fp16.h>

// ---------------------------------------------------------------------------
// TensorizedEmbedding: out[b] = core0[d0] x core1[d1] x core2[d2] x core3[d3]
// ROW_DIMS=(8,10,20,20), COL_DIMS=(4,4,6,8), RANKS=(1,16,16,16,1)
//
// R12: fp16 m16n8k16 MMA, per token 4x LDG.128 + 6x HMMA + 12 STG.64.
// R14 (= R13 retry, infra failure): steady-state is bound by dirty-L2
// writeback storms from the 100MB output (ncu cold-run hides this).
// Fix: st.global.wt output stores (write-through; paces DRAM writes, keeps
// L2 clean across graph replays). Precompute FB stages cores in smem.
// ---------------------------------------------------------------------------

// Fragment tables (fp16, MMA m16n8k16 register layout).
// g_FA[comb01][lane=32][reg=4][half=2]  (512B per combo, 40KB total)
// g_FB[comb23][ntp=3][lane=32][reg=4][half=2] (1.5KB per combo, 600KB total)
static __device__ __half g_FA[80 * 256];
static __device__ __half g_FB[400 * 768];

// Fused precompute into fp16 fragment layout: blocks 0..79 FA, 80..479 FB.
__global__ void precompute_frags(const float* __restrict__ core0,
                                 const float* __restrict__ core1,
                                 const float* __restrict__ core2,
                                 const float* __restrict__ core3) {
    if (blockIdx.x < 80) {
        int comb = blockIdx.x;                 // d0*10 + d1
        int d0 = comb / 10, d1 = comb % 10;
        int e   = threadIdx.x;                 // 0..255 = [lane][reg][half]
        int l   = e >> 3;
        int rr  = (e >> 1) & 3;
        int h   = e & 1;
        int row = (l >> 2) + (rr & 1) * 8;             // a (m-dim)
        int r2  = (l & 3) * 2 + h + (rr >> 1) * 8;     // k-dim
        int m0  = row >> 2, m1 = row & 3;
        float s = 0.f;
#pragma unroll
        for (int r1 = 0; r1 < 16; ++r1) {
            float v0 = core0[(d0 * 4 + m0) * 16 + r1];             // [1,8,4,16]
            float v1 = core1[((r1 * 10 + d1) * 4 + m1) * 16 + r2]; // [16,10,4,16]
            s += v0 * v1;
        }
        g_FA[comb * 256 + e] = __float2half_rn(s);
    } else {
        int comb = blockIdx.x - 80;            // d2*20 + d3
        int d2 = comb / 20, d3 = comb % 20;

        // Stage core2 slice [r2=16][m2=6][r3=16] and core3 slice [r3=16][m3=8]
        __shared__ float s2[1536];
        __shared__ float s3[128];
        for (int e = threadIdx.x; e < 1536; e += blockDim.x) {
            int r2 = e / 96, rest = e - r2 * 96;
            int m2 = rest >> 4, r3 = rest & 15;
            s2[e] = core2[((r2 * 20 + d2) * 6 + m2) * 16 + r3];
        }
        for (int e = threadIdx.x; e < 128; e += blockDim.x) {
            int r3 = e >> 3, m3 = e & 7;
            s3[e] = core3[(r3 * 20 + d3) * 8 + m3];
        }
        __syncthreads();

        for (int e = threadIdx.x; e < 768; e += blockDim.x) {
            int ntp = e >> 8;                  // 0..2 (nt pair)
            int r8  = e & 255;
            int l   = r8 >> 3;
            int rr  = (r8 >> 1) & 3;
            int h   = r8 & 1;
            int nt  = ntp * 2 + (rr >> 1);
            int brg = rr & 1;
            int k   = (l & 3) * 2 + h + brg * 8;   // r2 (k-dim)
            int n   = nt * 8 + (l >> 2);           // c  (n-dim)
            int m2  = n >> 3, m3 = n & 7;
            float s = 0.f;
#pragma unroll
            for (int r3 = 0; r3 < 16; ++r3)
                s += s2[(k * 6 + m2) * 16 + r3] * s3[r3 * 8 + m3];
            g_FB[comb * 768 + e] = __float2half_rn(s);
        }
    }
}

// ---------------------------------------------------------------------------

__device__ __forceinline__ void mma_f16(float* c, float4 a,
                                        unsigned b0, unsigned b1) {
    asm volatile(
        "mma.sync.aligned.m16n8k16.row.col.f32.f16.f16.f32 "
        "{%0,%1,%2,%3},{%4,%5,%6,%7},{%8,%9},{%0,%1,%2,%3};"
        : "+f"(c[0]), "+f"(c[1]), "+f"(c[2]), "+f"(c[3])
        : "r"(__float_as_uint(a.x)), "r"(__float_as_uint(a.y)),
          "r"(__float_as_uint(a.z)), "r"(__float_as_uint(a.w)),
          "r"(b0), "r"(b1));
}

// Write-through store: paces DRAM writes during the kernel and keeps L2
// clean of dirty output lines across graph replays.
__device__ __forceinline__ void stwt64_2f(float* p, float lo, float hi) {
    unsigned long long v;
    asm("mov.b64 %0, {%1, %2};" : "=l"(v) : "f"(lo), "f"(hi));
    asm volatile("st.global.wt.b64 [%0], %1;" :: "l"(p), "l"(v) : "memory");
}

#define T_PER_WARP 4
#define WARPS 8

__global__ __launch_bounds__(256)
void te_mma(const int* __restrict__ x, float* __restrict__ out, int B) {
    int w    = threadIdx.x >> 5;
    int lane = threadIdx.x & 31;
    int base = (blockIdx.x * WARPS + w) * T_PER_WARP;
    if (base >= B) return;

    // Coalesced x load for this warp's 4 tokens, distributed via shfl.
    int myx = 0;
    if (lane < T_PER_WARP && base + lane < B) myx = x[base + lane];

    int g  = lane >> 2;     // fragment row group
    int tq = lane & 3;      // thread-in-group

#pragma unroll
    for (int i = 0; i < T_PER_WARP; ++i) {
        int t = base + i;
        if (t >= B) break;
        int idx  = __shfl_sync(0xffffffffu, myx, i);
        int d01  = idx / 400;
        int comb = idx - d01 * 400;

        // A: one LDG.128 (512B/warp); B: three LDG.128 (nt pairs, 512B each)
        const float4* pA = (const float4*)g_FA + (size_t)d01 * 32 + lane;
        const float4* pB = (const float4*)g_FB + (size_t)comb * 96 + lane;

        float4 af = __ldg(pA);
        float4 b0 = __ldg(pB);
        float4 b1 = __ldg(pB + 32);
        float4 b2 = __ldg(pB + 64);

        float acc[6][4];
#pragma unroll
        for (int nt = 0; nt < 6; ++nt)
#pragma unroll
            for (int j = 0; j < 4; ++j) acc[nt][j] = 0.f;

        mma_f16(acc[0], af, __float_as_uint(b0.x), __float_as_uint(b0.y));
        mma_f16(acc[1], af, __float_as_uint(b0.z), __float_as_uint(b0.w));
        mma_f16(acc[2], af, __float_as_uint(b1.x), __float_as_uint(b1.y));
        mma_f16(acc[3], af, __float_as_uint(b1.z), __float_as_uint(b1.w));
        mma_f16(acc[4], af, __float_as_uint(b2.x), __float_as_uint(b2.y));
        mma_f16(acc[5], af, __float_as_uint(b2.z), __float_as_uint(b2.w));

        // D: c0,c1 -> row g cols tq*2,tq*2+1; c2,c3 -> row g+8.
        // Each (g,nt) group of 4 lanes fills one 32B sector completely.
        float* op = out + (size_t)t * 768 + g * 48 + tq * 2;
#pragma unroll
        for (int nt = 0; nt < 6; ++nt) {
            stwt64_2f(op + nt * 8,       acc[nt][0], acc[nt][1]);
            stwt64_2f(op + nt * 8 + 384, acc[nt][2], acc[nt][3]);  // +8 rows
        }
    }
}

// ---------------------------------------------------------------------------

extern "C" void kernel_launch(void* const* d_in, const int* in_sizes, int n_in,
                              void* d_out, int out_size) {
    // Identify inputs by element count (robust to ordering):
    // x: B (=32768), core0: 512, core1: 10240, core2: 30720, core3: 2560
    const int*   x  = nullptr;  int B = 0;
    const float* c0 = nullptr;
    const float* c1 = nullptr;
    const float* c2 = nullptr;
    const float* c3 = nullptr;
    for (int i = 0; i < n_in; ++i) {
        switch (in_sizes[i]) {
            case 512:   c0 = (const float*)d_in[i]; break;
            case 10240: c1 = (const float*)d_in[i]; break;
            case 30720: c2 = (const float*)d_in[i]; break;
            case 2560:  c3 = (const float*)d_in[i]; break;
            default:    x  = (const int*)d_in[i]; B = in_sizes[i]; break;
        }
    }

    precompute_frags<<<480, 256>>>(c0, c1, c2, c3);

    int tokPerBlock = WARPS * T_PER_WARP;            // 32
    int blocks = (B + tokPerBlock - 1) / tokPerBlock;
    te_mma<<<blocks, 256>>>(x, (float*)d_out, B);
}

// round 15
// speedup vs baseline: 2.4010x; 1.0677x over previous
#include <cuda_runtime.h>
#include <cuda_fp16.h>

// ---------------------------------------------------------------------------
// TensorizedEmbedding: out[b] = core0[d0] x core1[d1] x core2[d2] x core3[d3]
// ROW_DIMS=(8,10,20,20), COL_DIMS=(4,4,6,8), RANKS=(1,16,16,16,1)
//
// R12/R14: fp16 m16n8k16 MMA + st.global.wt (write-through keeps L2 clean
// across graph replays) -> 32.8us. R15:
//  (a) B fragments column-PERMUTED inside each nt-pair so each lane's 4
//      outputs per pair are contiguous -> 6x STG.128 instead of 12x STG.64.
//  (b) register double-buffering of next token's fragments (explicit MLP).
// ---------------------------------------------------------------------------

// Fragment tables (fp16, MMA m16n8k16 register layout).
// g_FA[comb01][lane=32][reg=4][half=2]  (512B per combo, 40KB total)
// g_FB[comb23][ntp=3][lane=32][reg=4][half=2] (1.5KB per combo, 600KB total)
//   Column permutation: fragment n-position p of sub-tile s in pair ntp maps
//   to global col  ntp*16 + (p>>1)*4 + s*2 + (p&1)  (lane-contiguous stores).
static __device__ __half g_FA[80 * 256];
static __device__ __half g_FB[400 * 768];

// Fused precompute into fp16 fragment layout: blocks 0..79 FA, 80..479 FB.
__global__ void precompute_frags(const float* __restrict__ core0,
                                 const float* __restrict__ core1,
                                 const float* __restrict__ core2,
                                 const float* __restrict__ core3) {
    if (blockIdx.x < 80) {
        int comb = blockIdx.x;                 // d0*10 + d1
        int d0 = comb / 10, d1 = comb % 10;
        int e   = threadIdx.x;                 // 0..255 = [lane][reg][half]
        int l   = e >> 3;
        int rr  = (e >> 1) & 3;
        int h   = e & 1;
        int row = (l >> 2) + (rr & 1) * 8;             // a (m-dim)
        int r2  = (l & 3) * 2 + h + (rr >> 1) * 8;     // k-dim
        int m0  = row >> 2, m1 = row & 3;
        float s = 0.f;
#pragma unroll
        for (int r1 = 0; r1 < 16; ++r1) {
            float v0 = core0[(d0 * 4 + m0) * 16 + r1];             // [1,8,4,16]
            float v1 = core1[((r1 * 10 + d1) * 4 + m1) * 16 + r2]; // [16,10,4,16]
            s += v0 * v1;
        }
        g_FA[comb * 256 + e] = __float2half_rn(s);
    } else {
        int comb = blockIdx.x - 80;            // d2*20 + d3
        int d2 = comb / 20, d3 = comb % 20;

        // Stage core2 slice [r2=16][m2=6][r3=16] and core3 slice [r3=16][m3=8]
        __shared__ float s2[1536];
        __shared__ float s3[128];
        for (int e = threadIdx.x; e < 1536; e += blockDim.x) {
            int r2 = e / 96, rest = e - r2 * 96;
            int m2 = rest >> 4, r3 = rest & 15;
            s2[e] = core2[((r2 * 20 + d2) * 6 + m2) * 16 + r3];
        }
        for (int e = threadIdx.x; e < 128; e += blockDim.x) {
            int r3 = e >> 3, m3 = e & 7;
            s3[e] = core3[(r3 * 20 + d3) * 8 + m3];
        }
        __syncthreads();

        for (int e = threadIdx.x; e < 768; e += blockDim.x) {
            int ntp = e >> 8;                  // 0..2 (nt pair)
            int r8  = e & 255;
            int l   = r8 >> 3;
            int rr  = (r8 >> 1) & 3;
            int h   = r8 & 1;
            int sts = rr >> 1;                 // sub-tile within pair (0/1)
            int brg = rr & 1;                  // b-register (k-halves)
            int k   = (l & 3) * 2 + h + brg * 8;   // r2 (k-dim)
            int p   = l >> 2;                  // fragment n-position (0..7)
            // PERMUTED global column: lane-contiguous across sub-tile pair
            int n   = ntp * 16 + (p >> 1) * 4 + sts * 2 + (p & 1);
            int m2  = n >> 3, m3 = n & 7;
            float s = 0.f;
#pragma unroll
            for (int r3 = 0; r3 < 16; ++r3)
                s += s2[(k * 6 + m2) * 16 + r3] * s3[r3 * 8 + m3];
            g_FB[comb * 768 + e] = __float2half_rn(s);
        }
    }
}

// ---------------------------------------------------------------------------

__device__ __forceinline__ void mma_f16(float* c, float4 a,
                                        unsigned b0, unsigned b1) {
    asm volatile(
        "mma.sync.aligned.m16n8k16.row.col.f32.f16.f16.f32 "
        "{%0,%1,%2,%3},{%4,%5,%6,%7},{%8,%9},{%0,%1,%2,%3};"
        : "+f"(c[0]), "+f"(c[1]), "+f"(c[2]), "+f"(c[3])
        : "r"(__float_as_uint(a.x)), "r"(__float_as_uint(a.y)),
          "r"(__float_as_uint(a.z)), "r"(__float_as_uint(a.w)),
          "r"(b0), "r"(b1));
}

// Write-through 128-bit store (paces DRAM writes, keeps L2 clean of dirty
// output lines across graph replays).
__device__ __forceinline__ void stwt128(float* p, float a, float b,
                                        float c, float d) {
    asm volatile("st.global.wt.v4.b32 [%0], {%1, %2, %3, %4};"
                 :: "l"(p), "f"(a), "f"(b), "f"(c), "f"(d) : "memory");
}

#define T_PER_WARP 4
#define WARPS 8

__global__ __launch_bounds__(256)
void te_mma(const int* __restrict__ x, float* __restrict__ out, int B) {
    int w    = threadIdx.x >> 5;
    int lane = threadIdx.x & 31;
    int base = (blockIdx.x * WARPS + w) * T_PER_WARP;
    if (base >= B) return;

    // Coalesced x load for this warp's 4 tokens, distributed via shfl.
    int myx = 0;
    if (lane < T_PER_WARP && base + lane < B) myx = x[base + lane];

    int g  = lane >> 2;     // fragment row group
    int tq = lane & 3;      // thread-in-group

    // Register double-buffer of fragments: slot = token parity.
    float4 A[2], B0[2], B1[2], B2[2];

    // Prefetch token 0.
    {
        int idx  = __shfl_sync(0xffffffffu, myx, 0);
        int d01  = idx / 400;
        int comb = idx - d01 * 400;
        const float4* pA = (const float4*)g_FA + (size_t)d01 * 32 + lane;
        const float4* pB = (const float4*)g_FB + (size_t)comb * 96 + lane;
        A[0]  = __ldg(pA);
        B0[0] = __ldg(pB);
        B1[0] = __ldg(pB + 32);
        B2[0] = __ldg(pB + 64);
    }

#pragma unroll
    for (int i = 0; i < T_PER_WARP; ++i) {
        int t = base + i;
        if (t >= B) break;
        int cur = i & 1;

        // Prefetch token i+1 into the other slot (MLP across iterations).
        if (i + 1 < T_PER_WARP && t + 1 < B) {
            int nxt  = (i + 1) & 1;
            int idx  = __shfl_sync(0xffffffffu, myx, i + 1);
            int d01  = idx / 400;
            int comb = idx - d01 * 400;
            const float4* pA = (const float4*)g_FA + (size_t)d01 * 32 + lane;
            const float4* pB = (const float4*)g_FB + (size_t)comb * 96 + lane;
            A[nxt]  = __ldg(pA);
            B0[nxt] = __ldg(pB);
            B1[nxt] = __ldg(pB + 32);
            B2[nxt] = __ldg(pB + 64);
        }

        float acc[6][4];
#pragma unroll
        for (int nt = 0; nt < 6; ++nt)
#pragma unroll
            for (int j = 0; j < 4; ++j) acc[nt][j] = 0.f;

        float4 af = A[cur];
        mma_f16(acc[0], af, __float_as_uint(B0[cur].x), __float_as_uint(B0[cur].y));
        mma_f16(acc[1], af, __float_as_uint(B0[cur].z), __float_as_uint(B0[cur].w));
        mma_f16(acc[2], af, __float_as_uint(B1[cur].x), __float_as_uint(B1[cur].y));
        mma_f16(acc[3], af, __float_as_uint(B1[cur].z), __float_as_uint(B1[cur].w));
        mma_f16(acc[4], af, __float_as_uint(B2[cur].x), __float_as_uint(B2[cur].y));
        mma_f16(acc[5], af, __float_as_uint(B2[cur].z), __float_as_uint(B2[cur].w));

        // Permuted layout: for pair ntp, this lane owns global cols
        // ntp*16 + tq*4 .. +3 on rows g and g+8 -> 6x STG.128 total.
        float* op = out + (size_t)t * 768 + g * 48 + tq * 4;
#pragma unroll
        for (int ntp = 0; ntp < 3; ++ntp) {
            int e = ntp * 2, o = e + 1;
            stwt128(op + ntp * 16,
                    acc[e][0], acc[e][1], acc[o][0], acc[o][1]);      // row g
            stwt128(op + ntp * 16 + 384,
                    acc[e][2], acc[e][3], acc[o][2], acc[o][3]);      // row g+8
        }
    }
}

// ---------------------------------------------------------------------------

extern "C" void kernel_launch(void* const* d_in, const int* in_sizes, int n_in,
                              void* d_out, int out_size) {
    // Identify inputs by element count (robust to ordering):
    // x: B (=32768), core0: 512, core1: 10240, core2: 30720, core3: 2560
    const int*   x  = nullptr;  int B = 0;
    const float* c0 = nullptr;
    const float* c1 = nullptr;
    const float* c2 = nullptr;
    const float* c3 = nullptr;
    for (int i = 0; i < n_in; ++i) {
        switch (in_sizes[i]) {
            case 512:   c0 = (const float*)d_in[i]; break;
            case 10240: c1 = (const float*)d_in[i]; break;
            case 30720: c2 = (const float*)d_in[i]; break;
            case 2560:  c3 = (const float*)d_in[i]; break;
            default:    x  = (const int*)d_in[i]; B = in_sizes[i]; break;
        }
    }

    precompute_frags<<<480, 256>>>(c0, c1, c2, c3);

    int tokPerBlock = WARPS * T_PER_WARP;            // 32
    int blocks = (B + tokPerBlock - 1) / tokPerBlock;
    te_mma<<<blocks, 256>>>(x, (float*)d_out, B);
}

// round 16
// speedup vs baseline: 2.4812x; 1.0334x over previous
#include <cuda_runtime.h>
#include <cuda_fp16.h>

// ---------------------------------------------------------------------------
// TensorizedEmbedding: out[b] = core0[d0] x core1[d1] x core2[d2] x core3[d3]
// ROW_DIMS=(8,10,20,20), COL_DIMS=(4,4,6,8), RANKS=(1,16,16,16,1)
//
// R15: fp16 m16n8k16 MMA, permuted-B STG.128, reg double-buffer, st.global.wt
// -> 30.7us total with ~10us outside the main kernel (precompute + launch).
// R16: Programmatic Dependent Launch — te_mma is launched with programmatic
// stream serialization and runs its table-independent prologue (x loads,
// index math) concurrently with precompute_frags; cudaGridDependencySynchronize
// gates the first table read. Implicit end-of-kernel trigger guarantees
// g_FA/g_FB visibility.
// ---------------------------------------------------------------------------

// Fragment tables (fp16, MMA m16n8k16 register layout).
// g_FA[comb01][lane=32][reg=4][half=2]  (512B per combo, 40KB total)
// g_FB[comb23][ntp=3][lane=32][reg=4][half=2] (1.5KB per combo, 600KB total)
//   Column permutation: fragment n-position p of sub-tile s in pair ntp maps
//   to global col  ntp*16 + (p>>1)*4 + s*2 + (p&1)  (lane-contiguous stores).
static __device__ __half g_FA[80 * 256];
static __device__ __half g_FB[400 * 768];

// Fused precompute into fp16 fragment layout: blocks 0..79 FA, 80..479 FB.
__global__ void precompute_frags(const float* __restrict__ core0,
                                 const float* __restrict__ core1,
                                 const float* __restrict__ core2,
                                 const float* __restrict__ core3) {
    if (blockIdx.x < 80) {
        int comb = blockIdx.x;                 // d0*10 + d1
        int d0 = comb / 10, d1 = comb % 10;
        int e   = threadIdx.x;                 // 0..255 = [lane][reg][half]
        int l   = e >> 3;
        int rr  = (e >> 1) & 3;
        int h   = e & 1;
        int row = (l >> 2) + (rr & 1) * 8;             // a (m-dim)
        int r2  = (l & 3) * 2 + h + (rr >> 1) * 8;     // k-dim
        int m0  = row >> 2, m1 = row & 3;
        float s = 0.f;
#pragma unroll
        for (int r1 = 0; r1 < 16; ++r1) {
            float v0 = core0[(d0 * 4 + m0) * 16 + r1];             // [1,8,4,16]
            float v1 = core1[((r1 * 10 + d1) * 4 + m1) * 16 + r2]; // [16,10,4,16]
            s += v0 * v1;
        }
        g_FA[comb * 256 + e] = __float2half_rn(s);
    } else {
        int comb = blockIdx.x - 80;            // d2*20 + d3
        int d2 = comb / 20, d3 = comb % 20;

        // Stage core2 slice [r2=16][m2=6][r3=16] and core3 slice [r3=16][m3=8]
        __shared__ float s2[1536];
        __shared__ float s3[128];
        for (int e = threadIdx.x; e < 1536; e += blockDim.x) {
            int r2 = e / 96, rest = e - r2 * 96;
            int m2 = rest >> 4, r3 = rest & 15;
            s2[e] = core2[((r2 * 20 + d2) * 6 + m2) * 16 + r3];
        }
        for (int e = threadIdx.x; e < 128; e += blockDim.x) {
            int r3 = e >> 3, m3 = e & 7;
            s3[e] = core3[(r3 * 20 + d3) * 8 + m3];
        }
        __syncthreads();

        for (int e = threadIdx.x; e < 768; e += blockDim.x) {
            int ntp = e >> 8;                  // 0..2 (nt pair)
            int r8  = e & 255;
            int l   = r8 >> 3;
            int rr  = (r8 >> 1) & 3;
            int h   = r8 & 1;
            int sts = rr >> 1;                 // sub-tile within pair (0/1)
            int brg = rr & 1;                  // b-register (k-halves)
            int k   = (l & 3) * 2 + h + brg * 8;   // r2 (k-dim)
            int p   = l >> 2;                  // fragment n-position (0..7)
            // PERMUTED global column: lane-contiguous across sub-tile pair
            int n   = ntp * 16 + (p >> 1) * 4 + sts * 2 + (p & 1);
            int m2  = n >> 3, m3 = n & 7;
            float s = 0.f;
#pragma unroll
            for (int r3 = 0; r3 < 16; ++r3)
                s += s2[(k * 6 + m2) * 16 + r3] * s3[r3 * 8 + m3];
            g_FB[comb * 768 + e] = __float2half_rn(s);
        }
    }
}

// ---------------------------------------------------------------------------

__device__ __forceinline__ void mma_f16(float* c, float4 a,
                                        unsigned b0, unsigned b1) {
    asm volatile(
        "mma.sync.aligned.m16n8k16.row.col.f32.f16.f16.f32 "
        "{%0,%1,%2,%3},{%4,%5,%6,%7},{%8,%9},{%0,%1,%2,%3};"
        : "+f"(c[0]), "+f"(c[1]), "+f"(c[2]), "+f"(c[3])
        : "r"(__float_as_uint(a.x)), "r"(__float_as_uint(a.y)),
          "r"(__float_as_uint(a.z)), "r"(__float_as_uint(a.w)),
          "r"(b0), "r"(b1));
}

// Write-through 128-bit store (paces DRAM writes, keeps L2 clean of dirty
// output lines across graph replays).
__device__ __forceinline__ void stwt128(float* p, float a, float b,
                                        float c, float d) {
    asm volatile("st.global.wt.v4.b32 [%0], {%1, %2, %3, %4};"
                 :: "l"(p), "f"(a), "f"(b), "f"(c), "f"(d) : "memory");
}

#define T_PER_WARP 4
#define WARPS 8

__global__ __launch_bounds__(256)
void te_mma(const int* __restrict__ x, float* __restrict__ out, int B) {
    int w    = threadIdx.x >> 5;
    int lane = threadIdx.x & 31;
    int base = (blockIdx.x * WARPS + w) * T_PER_WARP;
    if (base >= B) {
#if __CUDA_ARCH__ >= 900
        cudaGridDependencySynchronize();
#endif
        return;
    }

    // ---- table-independent prologue (overlaps precompute via PDL) ----
    int myx = 0;
    if (lane < T_PER_WARP && base + lane < B) myx = x[base + lane];

    int g  = lane >> 2;     // fragment row group
    int tq = lane & 3;      // thread-in-group

    int idx0  = __shfl_sync(0xffffffffu, myx, 0);
    int d01_0  = idx0 / 400;
    int comb_0 = idx0 - d01_0 * 400;

    // ---- wait for precompute's tables (implicit end-of-kernel trigger) ----
#if __CUDA_ARCH__ >= 900
    cudaGridDependencySynchronize();
#endif

    // Register double-buffer of fragments: slot = token parity.
    float4 A[2], B0[2], B1[2], B2[2];

    // Prefetch token 0.
    {
        const float4* pA = (const float4*)g_FA + (size_t)d01_0 * 32 + lane;
        const float4* pB = (const float4*)g_FB + (size_t)comb_0 * 96 + lane;
        A[0]  = __ldg(pA);
        B0[0] = __ldg(pB);
        B1[0] = __ldg(pB + 32);
        B2[0] = __ldg(pB + 64);
    }

#pragma unroll
    for (int i = 0; i < T_PER_WARP; ++i) {
        int t = base + i;
        if (t >= B) break;
        int cur = i & 1;

        // Prefetch token i+1 into the other slot (MLP across iterations).
        if (i + 1 < T_PER_WARP && t + 1 < B) {
            int nxt  = (i + 1) & 1;
            int idx  = __shfl_sync(0xffffffffu, myx, i + 1);
            int d01  = idx / 400;
            int comb = idx - d01 * 400;
            const float4* pA = (const float4*)g_FA + (size_t)d01 * 32 + lane;
            const float4* pB = (const float4*)g_FB + (size_t)comb * 96 + lane;
            A[nxt]  = __ldg(pA);
            B0[nxt] = __ldg(pB);
            B1[nxt] = __ldg(pB + 32);
            B2[nxt] = __ldg(pB + 64);
        }

        float acc[6][4];
#pragma unroll
        for (int nt = 0; nt < 6; ++nt)
#pragma unroll
            for (int j = 0; j < 4; ++j) acc[nt][j] = 0.f;

        float4 af = A[cur];
        mma_f16(acc[0], af, __float_as_uint(B0[cur].x), __float_as_uint(B0[cur].y));
        mma_f16(acc[1], af, __float_as_uint(B0[cur].z), __float_as_uint(B0[cur].w));
        mma_f16(acc[2], af, __float_as_uint(B1[cur].x), __float_as_uint(B1[cur].y));
        mma_f16(acc[3], af, __float_as_uint(B1[cur].z), __float_as_uint(B1[cur].w));
        mma_f16(acc[4], af, __float_as_uint(B2[cur].x), __float_as_uint(B2[cur].y));
        mma_f16(acc[5], af, __float_as_uint(B2[cur].z), __float_as_uint(B2[cur].w));

        // Permuted layout: for pair ntp, this lane owns global cols
        // ntp*16 + tq*4 .. +3 on rows g and g+8 -> 6x STG.128 total.
        float* op = out + (size_t)t * 768 + g * 48 + tq * 4;
#pragma unroll
        for (int ntp = 0; ntp < 3; ++ntp) {
            int e = ntp * 2, o = e + 1;
            stwt128(op + ntp * 16,
                    acc[e][0], acc[e][1], acc[o][0], acc[o][1]);      // row g
            stwt128(op + ntp * 16 + 384,
                    acc[e][2], acc[e][3], acc[o][2], acc[o][3]);      // row g+8
        }
    }
}

// ---------------------------------------------------------------------------

extern "C" void kernel_launch(void* const* d_in, const int* in_sizes, int n_in,
                              void* d_out, int out_size) {
    // Identify inputs by element count (robust to ordering):
    // x: B (=32768), core0: 512, core1: 10240, core2: 30720, core3: 2560
    const int*   x  = nullptr;  int B = 0;
    const float* c0 = nullptr;
    const float* c1 = nullptr;
    const float* c2 = nullptr;
    const float* c3 = nullptr;
    for (int i = 0; i < n_in; ++i) {
        switch (in_sizes[i]) {
            case 512:   c0 = (const float*)d_in[i]; break;
            case 10240: c1 = (const float*)d_in[i]; break;
            case 30720: c2 = (const float*)d_in[i]; break;
            case 2560:  c3 = (const float*)d_in[i]; break;
            default:    x  = (const int*)d_in[i]; B = in_sizes[i]; break;
        }
    }

    precompute_frags<<<480, 256>>>(c0, c1, c2, c3);

    int tokPerBlock = WARPS * T_PER_WARP;            // 32
    int blocks = (B + tokPerBlock - 1) / tokPerBlock;

    // Programmatic dependent launch: te_mma enters the pipe while
    // precompute_frags is still running; cudaGridDependencySynchronize()
    // inside te_mma gates the first table read.
    cudaLaunchConfig_t cfg = {};
    cfg.gridDim  = dim3((unsigned)blocks, 1, 1);
    cfg.blockDim = dim3(256, 1, 1);
    cfg.dynamicSmemBytes = 0;
    cfg.stream = 0;
    cudaLaunchAttribute attrs[1];
    attrs[0].id = cudaLaunchAttributeProgrammaticStreamSerialization;
    attrs[0].val.programmaticStreamSerializationAllowed = 1;
    cfg.attrs = attrs;
    cfg.numAttrs = 1;
    cudaLaunchKernelEx(&cfg, te_mma, x, (float*)d_out, B);
}